// round 13
// baseline (speedup 1.0000x reference)
#include <cuda_runtime.h>
#include <cuda_bf16.h>
#include <cuda_fp8.h>
#include <stdint.h>
#include <math.h>

#define H 8
#define D 128
#define KN 16
#define NNODES 10000
#define FIN 128

// ---- scratch (static device globals; no allocation allowed) ----
__device__ unsigned char g_h8[H * NNODES * D];     // 10.2 MB fp8 (e4m3) features
__device__ unsigned char g_a8[NNODES * FIN];       // fp8 X / emb buffer (1.28 MB)
__device__ unsigned char g_w8[3 * H * D * FIN];    // fp8 weights (384 KB)
__device__ float g_ssrc[H * NNODES];
__device__ float g_sdst[H * NNODES];
__device__ float g_gsum[D];

// ============================================================================
// Merged fp32 -> fp8(e4m3) converter: X + W1 + W2 + W3, plus g_gsum zeroing.
// ============================================================================
#define NX4 (NNODES * FIN / 4)     // 320000 float4s
#define NW4 (H * D * FIN / 4)      // 32768 float4s per weight
#define TOTC (NX4 + 3 * NW4)       // 418304
__global__ void cvt_all(const float* __restrict__ x,  const float* __restrict__ w1,
                        const float* __restrict__ w2, const float* __restrict__ w3)
{
    const int i = blockIdx.x * blockDim.x + threadIdx.x;
    const float* src; unsigned char* dst; int j;
    if (i < NX4)               { src = x;  dst = g_a8;                 j = i; }
    else if (i < NX4 + NW4)    { src = w1; dst = g_w8;                 j = i - NX4; }
    else if (i < NX4 + 2*NW4)  { src = w2; dst = g_w8 + H*D*FIN;       j = i - NX4 - NW4; }
    else if (i < TOTC)         { src = w3; dst = g_w8 + 2*H*D*FIN;     j = i - NX4 - 2*NW4; }
    else {
        const int z = i - TOTC;
        if (z < D) g_gsum[z] = 0.f;
        return;
    }
    const float4 v = ((const float4*)src)[j];
    const uint32_t lo = __nv_cvt_float2_to_fp8x2(make_float2(v.x, v.y), __NV_SATFINITE, __NV_E4M3);
    const uint32_t hi = __nv_cvt_float2_to_fp8x2(make_float2(v.z, v.w), __NV_SATFINITE, __NV_E4M3);
    *(uint32_t*)(dst + j * 4) = (hi << 16) | (lo & 0xffffu);
}

// ============================================================================
// Kernel 1: per-head GEMM via FP8 tensor cores (mma.m16n8k32 e4m3, fp32 accum).
// (Frozen from round 12: best measured config.)
// ============================================================================
#define BM 128
#define AS72 72
#define TILE_B16 (BM * AS72)
#define STR 68

__device__ __forceinline__ void mma_fp8(float* c, const uint32_t* a, const uint32_t* b)
{
    asm volatile(
        "mma.sync.aligned.m16n8k32.row.col.f32.e4m3.e4m3.f32 "
        "{%0,%1,%2,%3}, {%4,%5,%6,%7}, {%8,%9}, {%0,%1,%2,%3};"
        : "+f"(c[0]), "+f"(c[1]), "+f"(c[2]), "+f"(c[3])
        : "r"(a[0]), "r"(a[1]), "r"(a[2]), "r"(a[3]), "r"(b[0]), "r"(b[1]));
}

__device__ __forceinline__ void ldsm4(uint32_t* r, uint32_t saddr)
{
    asm volatile("ldmatrix.sync.aligned.m8n8.x4.shared.b16 {%0,%1,%2,%3}, [%4];"
                 : "=r"(r[0]), "=r"(r[1]), "=r"(r[2]), "=r"(r[3]) : "r"(saddr));
}

__device__ __forceinline__ void cp16(uint32_t saddr, const void* gaddr, int srcsz)
{
    asm volatile("cp.async.cg.shared.global [%0], [%1], 16, %2;"
                 :: "r"(saddr), "l"(gaddr), "r"(srcsz));
}

__device__ __forceinline__ void cp_commit()
{ asm volatile("cp.async.commit_group;" ::: "memory"); }

__device__ __forceinline__ void cp_wait0()
{ asm volatile("cp.async.wait_group 0;" ::: "memory"); }

__global__ __launch_bounds__(256, 2) void gat_gemm(
    const unsigned char* __restrict__ A, const unsigned char* __restrict__ W,
    const float* __restrict__ avec)
{
    const int h  = blockIdx.y;
    const int n0 = blockIdx.x * BM;
    const int tid = threadIdx.x;
    const int wid = tid >> 5, lane = tid & 31;
    const int warp_m = wid >> 1;
    const int warp_n = wid & 1;
    const int g = lane >> 2, t = lane & 3;

    __shared__ __align__(16) unsigned char s_tiles[2 * TILE_B16 * 2];
    __shared__ float s_as[D], s_ad[D];

    __nv_bfloat16* As = (__nv_bfloat16*)s_tiles;
    __nv_bfloat16* Bs = (__nv_bfloat16*)(s_tiles + TILE_B16 * 2);
    float* stg = (float*)s_tiles;

    if (tid < D) {
        s_as[tid] = avec[h * 2 * D + tid];
        s_ad[tid] = avec[h * 2 * D + D + tid];
    }

    const unsigned char* Wh = W + (size_t)h * D * FIN;
    const uint32_t as_base = (uint32_t)__cvta_generic_to_shared(As);
    const uint32_t bs_base = (uint32_t)__cvta_generic_to_shared(Bs);

#pragma unroll
    for (int i = 0; i < 4; i++) {
        const int v = tid + i * 256;
        const int row = v >> 3;
        const int cb  = (v & 7) * 16;
        const uint32_t so = (uint32_t)(row * 144 + cb);
        const int gr = n0 + row;
        cp16(as_base + so, A + (size_t)gr * FIN + cb, gr < NNODES ? 16 : 0);
        cp16(bs_base + so, Wh + (size_t)row * FIN + cb, 16);
    }
    cp_commit();
    cp_wait0();
    __syncthreads();

    float acc[2][8][4];
#pragma unroll
    for (int mt = 0; mt < 2; mt++)
#pragma unroll
        for (int nt = 0; nt < 8; nt++)
#pragma unroll
            for (int i = 0; i < 4; i++) acc[mt][nt][i] = 0.f;

#pragma unroll
    for (int ks = 0; ks < 64; ks += 16) {
        uint32_t b[8][2];
#pragma unroll
        for (int np = 0; np < 4; np++) {
            const int row = warp_n * 64 + np * 16 + (lane & 7) + ((lane >> 4) << 3);
            const int col = ks + (((lane >> 3) & 1) << 3);
            uint32_t r[4];
            ldsm4(r, bs_base + (uint32_t)(row * AS72 + col) * 2);
            b[2*np][0] = r[0]; b[2*np][1] = r[1];
            b[2*np+1][0] = r[2]; b[2*np+1][1] = r[3];
        }
#pragma unroll
        for (int mt = 0; mt < 2; mt++) {
            const int row = warp_m * 32 + mt * 16 + (lane & 7) + (((lane >> 3) & 1) << 3);
            const int col = ks + ((lane >> 4) << 3);
            uint32_t a[4];
            ldsm4(a, as_base + (uint32_t)(row * AS72 + col) * 2);
#pragma unroll
            for (int nt = 0; nt < 8; nt++) mma_fp8(acc[mt][nt], a, b[nt]);
        }
    }
    __syncthreads();

    const int row  = tid >> 1;
    const int half = tid & 1;
    const int n    = n0 + row;
    float lss = 0.f, lsd = 0.f;

#pragma unroll
    for (int p = 0; p < 2; p++) {
        if (warp_n == p) {
#pragma unroll
            for (int mt = 0; mt < 2; mt++) {
                const int r0 = warp_m * 32 + mt * 16 + g;
#pragma unroll
                for (int nt = 0; nt < 8; nt++) {
                    const int c = nt * 8 + 2 * t;
                    stg[r0 * STR + c]           = acc[mt][nt][0];
                    stg[r0 * STR + c + 1]       = acc[mt][nt][1];
                    stg[(r0 + 8) * STR + c]     = acc[mt][nt][2];
                    stg[(r0 + 8) * STR + c + 1] = acc[mt][nt][3];
                }
            }
        }
        __syncthreads();

        const int cb = half * 32;
        uint32_t packed[8];
#pragma unroll
        for (int q = 0; q < 8; q++) {
            const float4 v = *(const float4*)&stg[row * STR + cb + q * 4];
            const int sc = p * 64 + cb + q * 4;
            lss += v.x * s_as[sc] + v.y * s_as[sc+1] + v.z * s_as[sc+2] + v.w * s_as[sc+3];
            lsd += v.x * s_ad[sc] + v.y * s_ad[sc+1] + v.z * s_ad[sc+2] + v.w * s_ad[sc+3];
            const uint32_t lo = __nv_cvt_float2_to_fp8x2(make_float2(v.x, v.y), __NV_SATFINITE, __NV_E4M3);
            const uint32_t hi = __nv_cvt_float2_to_fp8x2(make_float2(v.z, v.w), __NV_SATFINITE, __NV_E4M3);
            packed[q] = (hi << 16) | (lo & 0xffffu);
        }
        if (n < NNODES) {
            uint4* dst = (uint4*)&g_h8[((size_t)h * NNODES + n) * D + p * 64 + cb];
            dst[0] = make_uint4(packed[0], packed[1], packed[2], packed[3]);
            dst[1] = make_uint4(packed[4], packed[5], packed[6], packed[7]);
        }
        __syncthreads();
    }

    lss += __shfl_xor_sync(0xffffffffu, lss, 1);
    lsd += __shfl_xor_sync(0xffffffffu, lsd, 1);
    if (half == 0 && n < NNODES) {
        g_ssrc[h * NNODES + n] = lss;
        g_sdst[h * NNODES + n] = lsd;
    }
}

// ============================================================================
// Kernel 2: attention. 1 block/node, 1 warp/head. uint4 gathers (16 fp8 per
// lane, 8 lanes/row, 4 nbrs/warp-iter), fp16 HFMA2 accumulation.
// last=0: write fp8 emb to g_a8; last=1: fused node-mean via fp32 atomicAdd.
// ============================================================================
__device__ __forceinline__ __half2 fp8x2_to_h2(unsigned short s)
{
    __half2_raw r = __nv_cvt_fp8x2_to_halfraw2((__nv_fp8x2_storage_t)s, __NV_E4M3);
    return *reinterpret_cast<__half2*>(&r);
}

__global__ __launch_bounds__(256) void gat_attn(const int* __restrict__ nbr, int last)
{
    const int n = blockIdx.x;
    const int tid = threadIdx.x;
    const int w = tid >> 5, lane = tid & 31;
    __shared__ float hacc[H][D];

    int idx = 0;
    float e = -1e30f;
    if (lane < KN) {
        idx = nbr[n * KN + lane];
        const float v = g_ssrc[w * NNODES + n] + g_sdst[w * NNODES + idx];
        e = v > 0.f ? v : 0.01f * v;
    }
    float mx = e;
#pragma unroll
    for (int s = 16; s >= 1; s >>= 1) mx = fmaxf(mx, __shfl_xor_sync(0xffffffffu, mx, s));
    const float ex = (lane < KN) ? expf(e - mx) : 0.f;
    float sum = ex;
#pragma unroll
    for (int s = 16; s >= 1; s >>= 1) sum += __shfl_xor_sync(0xffffffffu, sum, s);
    const float alpha = ex / sum;

    __half2 ah2 = __float2half2_rn(alpha);
    const uint32_t habits = *reinterpret_cast<uint32_t*>(&ah2);

    const unsigned char* hb = g_h8 + (size_t)w * NNODES * D;   // 128 B per row
    const int sub  = lane >> 3;               // 0..3: which neighbor of the quad
    const int colb = (lane & 7) * 16;         // byte offset (16 elems) within 128B row

    __half2 acc[8];
#pragma unroll
    for (int j = 0; j < 8; j++) acc[j] = __float2half2_rn(0.f);

#pragma unroll
    for (int i = 0; i < 4; i++) {
        const int src = 4 * i + sub;
        const uint32_t ab = __shfl_sync(0xffffffffu, habits, src);
        const int ix = __shfl_sync(0xffffffffu, idx, src);
        const uint4 v = *(const uint4*)(hb + (((unsigned)ix) << 7) + colb);
        const __half2 av = *reinterpret_cast<const __half2*>(&ab);
        acc[0] = __hfma2(av, fp8x2_to_h2((unsigned short)(v.x & 0xffffu)), acc[0]);
        acc[1] = __hfma2(av, fp8x2_to_h2((unsigned short)(v.x >> 16)),     acc[1]);
        acc[2] = __hfma2(av, fp8x2_to_h2((unsigned short)(v.y & 0xffffu)), acc[2]);
        acc[3] = __hfma2(av, fp8x2_to_h2((unsigned short)(v.y >> 16)),     acc[3]);
        acc[4] = __hfma2(av, fp8x2_to_h2((unsigned short)(v.z & 0xffffu)), acc[4]);
        acc[5] = __hfma2(av, fp8x2_to_h2((unsigned short)(v.z >> 16)),     acc[5]);
        acc[6] = __hfma2(av, fp8x2_to_h2((unsigned short)(v.w & 0xffffu)), acc[6]);
        acc[7] = __hfma2(av, fp8x2_to_h2((unsigned short)(v.w >> 16)),     acc[7]);
    }
    // combine the four 8-lane groups (xor 16, then xor 8)
#pragma unroll
    for (int j = 0; j < 8; j++) {
        uint32_t b = *reinterpret_cast<uint32_t*>(&acc[j]);
        uint32_t o = __shfl_xor_sync(0xffffffffu, b, 16);
        acc[j] = __hadd2(acc[j], *(const __half2*)&o);
        b = *reinterpret_cast<uint32_t*>(&acc[j]);
        o = __shfl_xor_sync(0xffffffffu, b, 8);
        acc[j] = __hadd2(acc[j], *(const __half2*)&o);
    }
    if (lane < 8) {
        // lane owns dims [lane*16, lane*16+16)
        float* hp = &hacc[w][lane * 16];
#pragma unroll
        for (int j = 0; j < 4; j++) {
            const float2 fa = __half22float2(acc[2*j]);
            const float2 fb = __half22float2(acc[2*j+1]);
            ((float4*)hp)[j] = make_float4(fa.x, fa.y, fb.x, fb.y);
        }
    }
    __syncthreads();

    if (tid < D) {
        float s = 0.f;
#pragma unroll
        for (int hh = 0; hh < H; hh++) s += hacc[hh][tid];
        s *= 0.125f;                       // mean over heads
        s = s > 0.f ? s : expm1f(s);       // ELU (alpha=1)
        if (last) {
            atomicAdd(&g_gsum[tid], s);    // fused node-mean (fp32)
        } else {
            g_a8[(size_t)n * D + tid] =
                (unsigned char)__nv_cvt_float_to_fp8(s, __NV_SATFINITE, __NV_E4M3);
        }
    }
}

// ============================================================================
// Tiny MLP on g = gsum / N
// ============================================================================
__global__ void mlp_kernel(
    const float* __restrict__ ln1_g, const float* __restrict__ ln1_b,
    const float* __restrict__ lin1_W,
    const float* __restrict__ ln2_g, const float* __restrict__ ln2_b,
    const float* __restrict__ lin2_W, const float* __restrict__ lin2_b,
    const float* __restrict__ ln3_g, const float* __restrict__ ln3_b,
    const float* __restrict__ lin3_W, const float* __restrict__ lin3_b,
    const float* __restrict__ lin4_W, const float* __restrict__ lin4_b,
    float* __restrict__ out)
{
    __shared__ float buf[128];
    __shared__ float stat[2];
    const int t = threadIdx.x;   // 128 threads

    buf[t] = g_gsum[t] * (1.0f / NNODES);
    __syncthreads();

    // LN1 (len 128)
    if (t == 0) { float s=0; for (int i=0;i<128;i++) s+=buf[i]; stat[0]=s/128.f; }
    __syncthreads();
    if (t == 0) { float s=0; for (int i=0;i<128;i++){float d=buf[i]-stat[0]; s+=d*d;} stat[1]=s/128.f; }
    __syncthreads();
    float xv = (buf[t]-stat[0]) * rsqrtf(stat[1]+1e-5f) * ln1_g[t] + ln1_b[t];
    __syncthreads(); buf[t] = xv; __syncthreads();

    // lin1 (64x128, no bias) + exact GELU
    float o = 0.f;
    if (t < 64) {
        for (int d = 0; d < 128; d++) o += buf[d] * lin1_W[t*128 + d];
        o = o * normcdff(o);
    }
    __syncthreads(); if (t < 64) buf[t] = o; __syncthreads();

    // LN2 (len 64)
    if (t == 0) { float s=0; for (int i=0;i<64;i++) s+=buf[i]; stat[0]=s/64.f; }
    __syncthreads();
    if (t == 0) { float s=0; for (int i=0;i<64;i++){float d=buf[i]-stat[0]; s+=d*d;} stat[1]=s/64.f; }
    __syncthreads();
    if (t < 64) xv = (buf[t]-stat[0]) * rsqrtf(stat[1]+1e-5f) * ln2_g[t] + ln2_b[t];
    __syncthreads(); if (t < 64) buf[t] = xv; __syncthreads();

    // lin2 (32x64) + bias + GELU
    if (t < 32) {
        o = lin2_b[t];
        for (int d = 0; d < 64; d++) o += buf[d] * lin2_W[t*64 + d];
        o = o * normcdff(o);
    }
    __syncthreads(); if (t < 32) buf[t] = o; __syncthreads();

    // LN3 (len 32)
    if (t == 0) { float s=0; for (int i=0;i<32;i++) s+=buf[i]; stat[0]=s/32.f; }
    __syncthreads();
    if (t == 0) { float s=0; for (int i=0;i<32;i++){float d=buf[i]-stat[0]; s+=d*d;} stat[1]=s/32.f; }
    __syncthreads();
    if (t < 32) xv = (buf[t]-stat[0]) * rsqrtf(stat[1]+1e-5f) * ln3_g[t] + ln3_b[t];
    __syncthreads(); if (t < 32) buf[t] = xv; __syncthreads();

    // lin3 (8x32) + bias + GELU
    if (t < 8) {
        o = lin3_b[t];
        for (int d = 0; d < 32; d++) o += buf[d] * lin3_W[t*32 + d];
        o = o * normcdff(o);
    }
    __syncthreads(); if (t < 8) buf[t] = o; __syncthreads();

    // lin4 (1x8) + bias + ReLU
    if (t == 0) {
        float r = lin4_b[0];
        for (int i = 0; i < 8; i++) r += buf[i] * lin4_W[i];
        out[0] = fmaxf(r, 0.f);
    }
}

// ============================================================================
extern "C" void kernel_launch(void* const* d_in, const int* in_sizes, int n_in,
                              void* d_out, int out_size)
{
    const float* xf    = (const float*)d_in[0];
    const int*   nbr   = (const int*)  d_in[1];
    const float* W1    = (const float*)d_in[2];
    const float* a1    = (const float*)d_in[3];
    const float* W2    = (const float*)d_in[4];
    const float* a2    = (const float*)d_in[5];
    const float* W3    = (const float*)d_in[6];
    const float* a3    = (const float*)d_in[7];
    const float* ln1_g = (const float*)d_in[8];
    const float* ln1_b = (const float*)d_in[9];
    const float* lin1_W= (const float*)d_in[10];
    const float* ln2_g = (const float*)d_in[11];
    const float* ln2_b = (const float*)d_in[12];
    const float* lin2_W= (const float*)d_in[13];
    const float* lin2_b= (const float*)d_in[14];
    const float* ln3_g = (const float*)d_in[15];
    const float* ln3_b = (const float*)d_in[16];
    const float* lin3_W= (const float*)d_in[17];
    const float* lin3_b= (const float*)d_in[18];
    const float* lin4_W= (const float*)d_in[19];
    const float* lin4_b= (const float*)d_in[20];
    float* out = (float*)d_out;

    unsigned char *abp = nullptr, *wbp = nullptr;
    cudaGetSymbolAddress((void**)&abp, g_a8);
    cudaGetSymbolAddress((void**)&wbp, g_w8);

    const int WSZ = H * D * FIN;                       // 131072
    cvt_all<<<(TOTC + D + 255) / 256, 256>>>(xf, W1, W2, W3);

    const dim3 ggrid((NNODES + BM - 1) / BM, H);   // (79, 8)

    gat_gemm<<<ggrid, 256>>>(abp, wbp,            a1);
    gat_attn<<<NNODES, 256>>>(nbr, 0);
    gat_gemm<<<ggrid, 256>>>(abp, wbp + WSZ,      a2);
    gat_attn<<<NNODES, 256>>>(nbr, 0);
    gat_gemm<<<ggrid, 256>>>(abp, wbp + 2 * WSZ,  a3);
    gat_attn<<<NNODES, 256>>>(nbr, 1);

    mlp_kernel<<<1, 128>>>(ln1_g, ln1_b, lin1_W, ln2_g, ln2_b, lin2_W, lin2_b,
                           ln3_g, ln3_b, lin3_W, lin3_b, lin4_W, lin4_b, out);
    (void)in_sizes; (void)n_in; (void)out_size;
}

// round 14
// speedup vs baseline: 1.0225x; 1.0225x over previous
#include <cuda_runtime.h>
#include <cuda_bf16.h>
#include <cuda_fp8.h>
#include <stdint.h>
#include <math.h>

#define H 8
#define D 128
#define KN 16
#define NNODES 10000
#define FIN 128

// ---- scratch (static device globals; no allocation allowed) ----
__device__ unsigned char g_h8[H * NNODES * D];     // 10.2 MB fp8 (e4m3) features
__device__ unsigned char g_a8[NNODES * FIN];       // fp8 X / emb buffer (1.28 MB)
__device__ unsigned char g_w8[3 * H * D * FIN];    // fp8 weights (384 KB)
__device__ float g_ssrc[H * NNODES];
__device__ float g_sdst[H * NNODES];
__device__ float g_gsum[D];

// ============================================================================
// Merged fp32 -> fp8(e4m3) converter: X + W1 + W2 + W3, plus g_gsum zeroing.
// ============================================================================
#define NX4 (NNODES * FIN / 4)     // 320000 float4s
#define NW4 (H * D * FIN / 4)      // 32768 float4s per weight
#define TOTC (NX4 + 3 * NW4)       // 418304
__global__ void cvt_all(const float* __restrict__ x,  const float* __restrict__ w1,
                        const float* __restrict__ w2, const float* __restrict__ w3)
{
    const int i = blockIdx.x * blockDim.x + threadIdx.x;
    const float* src; unsigned char* dst; int j;
    if (i < NX4)               { src = x;  dst = g_a8;                 j = i; }
    else if (i < NX4 + NW4)    { src = w1; dst = g_w8;                 j = i - NX4; }
    else if (i < NX4 + 2*NW4)  { src = w2; dst = g_w8 + H*D*FIN;       j = i - NX4 - NW4; }
    else if (i < TOTC)         { src = w3; dst = g_w8 + 2*H*D*FIN;     j = i - NX4 - 2*NW4; }
    else {
        const int z = i - TOTC;
        if (z < D) g_gsum[z] = 0.f;
        return;
    }
    const float4 v = ((const float4*)src)[j];
    const uint32_t lo = __nv_cvt_float2_to_fp8x2(make_float2(v.x, v.y), __NV_SATFINITE, __NV_E4M3);
    const uint32_t hi = __nv_cvt_float2_to_fp8x2(make_float2(v.z, v.w), __NV_SATFINITE, __NV_E4M3);
    *(uint32_t*)(dst + j * 4) = (hi << 16) | (lo & 0xffffu);
}

// ============================================================================
// Kernel 1: per-head GEMM via FP8 tensor cores (mma.m16n8k32 e4m3, fp32 accum).
// (Frozen from round 12: best measured config.)
// ============================================================================
#define BM 128
#define AS72 72
#define TILE_B16 (BM * AS72)
#define STR 68

__device__ __forceinline__ void mma_fp8(float* c, const uint32_t* a, const uint32_t* b)
{
    asm volatile(
        "mma.sync.aligned.m16n8k32.row.col.f32.e4m3.e4m3.f32 "
        "{%0,%1,%2,%3}, {%4,%5,%6,%7}, {%8,%9}, {%0,%1,%2,%3};"
        : "+f"(c[0]), "+f"(c[1]), "+f"(c[2]), "+f"(c[3])
        : "r"(a[0]), "r"(a[1]), "r"(a[2]), "r"(a[3]), "r"(b[0]), "r"(b[1]));
}

__device__ __forceinline__ void ldsm4(uint32_t* r, uint32_t saddr)
{
    asm volatile("ldmatrix.sync.aligned.m8n8.x4.shared.b16 {%0,%1,%2,%3}, [%4];"
                 : "=r"(r[0]), "=r"(r[1]), "=r"(r[2]), "=r"(r[3]) : "r"(saddr));
}

__device__ __forceinline__ void cp16(uint32_t saddr, const void* gaddr, int srcsz)
{
    asm volatile("cp.async.cg.shared.global [%0], [%1], 16, %2;"
                 :: "r"(saddr), "l"(gaddr), "r"(srcsz));
}

__device__ __forceinline__ void cp_commit()
{ asm volatile("cp.async.commit_group;" ::: "memory"); }

__device__ __forceinline__ void cp_wait0()
{ asm volatile("cp.async.wait_group 0;" ::: "memory"); }

__global__ __launch_bounds__(256, 2) void gat_gemm(
    const unsigned char* __restrict__ A, const unsigned char* __restrict__ W,
    const float* __restrict__ avec)
{
    const int h  = blockIdx.y;
    const int n0 = blockIdx.x * BM;
    const int tid = threadIdx.x;
    const int wid = tid >> 5, lane = tid & 31;
    const int warp_m = wid >> 1;
    const int warp_n = wid & 1;
    const int g = lane >> 2, t = lane & 3;

    __shared__ __align__(16) unsigned char s_tiles[2 * TILE_B16 * 2];
    __shared__ float s_as[D], s_ad[D];

    __nv_bfloat16* As = (__nv_bfloat16*)s_tiles;
    __nv_bfloat16* Bs = (__nv_bfloat16*)(s_tiles + TILE_B16 * 2);
    float* stg = (float*)s_tiles;

    if (tid < D) {
        s_as[tid] = avec[h * 2 * D + tid];
        s_ad[tid] = avec[h * 2 * D + D + tid];
    }

    const unsigned char* Wh = W + (size_t)h * D * FIN;
    const uint32_t as_base = (uint32_t)__cvta_generic_to_shared(As);
    const uint32_t bs_base = (uint32_t)__cvta_generic_to_shared(Bs);

#pragma unroll
    for (int i = 0; i < 4; i++) {
        const int v = tid + i * 256;
        const int row = v >> 3;
        const int cb  = (v & 7) * 16;
        const uint32_t so = (uint32_t)(row * 144 + cb);
        const int gr = n0 + row;
        cp16(as_base + so, A + (size_t)gr * FIN + cb, gr < NNODES ? 16 : 0);
        cp16(bs_base + so, Wh + (size_t)row * FIN + cb, 16);
    }
    cp_commit();
    cp_wait0();
    __syncthreads();

    float acc[2][8][4];
#pragma unroll
    for (int mt = 0; mt < 2; mt++)
#pragma unroll
        for (int nt = 0; nt < 8; nt++)
#pragma unroll
            for (int i = 0; i < 4; i++) acc[mt][nt][i] = 0.f;

#pragma unroll
    for (int ks = 0; ks < 64; ks += 16) {
        uint32_t b[8][2];
#pragma unroll
        for (int np = 0; np < 4; np++) {
            const int row = warp_n * 64 + np * 16 + (lane & 7) + ((lane >> 4) << 3);
            const int col = ks + (((lane >> 3) & 1) << 3);
            uint32_t r[4];
            ldsm4(r, bs_base + (uint32_t)(row * AS72 + col) * 2);
            b[2*np][0] = r[0]; b[2*np][1] = r[1];
            b[2*np+1][0] = r[2]; b[2*np+1][1] = r[3];
        }
#pragma unroll
        for (int mt = 0; mt < 2; mt++) {
            const int row = warp_m * 32 + mt * 16 + (lane & 7) + (((lane >> 3) & 1) << 3);
            const int col = ks + ((lane >> 4) << 3);
            uint32_t a[4];
            ldsm4(a, as_base + (uint32_t)(row * AS72 + col) * 2);
#pragma unroll
            for (int nt = 0; nt < 8; nt++) mma_fp8(acc[mt][nt], a, b[nt]);
        }
    }
    __syncthreads();

    const int row  = tid >> 1;
    const int half = tid & 1;
    const int n    = n0 + row;
    float lss = 0.f, lsd = 0.f;

#pragma unroll
    for (int p = 0; p < 2; p++) {
        if (warp_n == p) {
#pragma unroll
            for (int mt = 0; mt < 2; mt++) {
                const int r0 = warp_m * 32 + mt * 16 + g;
#pragma unroll
                for (int nt = 0; nt < 8; nt++) {
                    const int c = nt * 8 + 2 * t;
                    stg[r0 * STR + c]           = acc[mt][nt][0];
                    stg[r0 * STR + c + 1]       = acc[mt][nt][1];
                    stg[(r0 + 8) * STR + c]     = acc[mt][nt][2];
                    stg[(r0 + 8) * STR + c + 1] = acc[mt][nt][3];
                }
            }
        }
        __syncthreads();

        const int cb = half * 32;
        uint32_t packed[8];
#pragma unroll
        for (int q = 0; q < 8; q++) {
            const float4 v = *(const float4*)&stg[row * STR + cb + q * 4];
            const int sc = p * 64 + cb + q * 4;
            lss += v.x * s_as[sc] + v.y * s_as[sc+1] + v.z * s_as[sc+2] + v.w * s_as[sc+3];
            lsd += v.x * s_ad[sc] + v.y * s_ad[sc+1] + v.z * s_ad[sc+2] + v.w * s_ad[sc+3];
            const uint32_t lo = __nv_cvt_float2_to_fp8x2(make_float2(v.x, v.y), __NV_SATFINITE, __NV_E4M3);
            const uint32_t hi = __nv_cvt_float2_to_fp8x2(make_float2(v.z, v.w), __NV_SATFINITE, __NV_E4M3);
            packed[q] = (hi << 16) | (lo & 0xffffu);
        }
        if (n < NNODES) {
            uint4* dst = (uint4*)&g_h8[((size_t)h * NNODES + n) * D + p * 64 + cb];
            dst[0] = make_uint4(packed[0], packed[1], packed[2], packed[3]);
            dst[1] = make_uint4(packed[4], packed[5], packed[6], packed[7]);
        }
        __syncthreads();
    }

    lss += __shfl_xor_sync(0xffffffffu, lss, 1);
    lsd += __shfl_xor_sync(0xffffffffu, lsd, 1);
    if (half == 0 && n < NNODES) {
        g_ssrc[h * NNODES + n] = lss;
        g_sdst[h * NNODES + n] = lsd;
    }
}

// ============================================================================
// Kernel 2: attention (round-12 gather structure: uint2, 16 lanes/row,
// 2 nbrs/iter, 4 half2 accumulators, single xor-16 combine).
// last=0: write fp8 emb to g_a8; last=1: fused node-mean via fp32 atomicAdd.
// ============================================================================
__device__ __forceinline__ __half2 fp8x2_to_h2(unsigned short s)
{
    __half2_raw r = __nv_cvt_fp8x2_to_halfraw2((__nv_fp8x2_storage_t)s, __NV_E4M3);
    return *reinterpret_cast<__half2*>(&r);
}

__global__ __launch_bounds__(256) void gat_attn(const int* __restrict__ nbr, int last)
{
    const int n = blockIdx.x;
    const int tid = threadIdx.x;
    const int w = tid >> 5, lane = tid & 31;
    __shared__ float hacc[H][D];

    int idx = 0;
    float e = -1e30f;
    if (lane < KN) {
        idx = nbr[n * KN + lane];
        const float v = g_ssrc[w * NNODES + n] + g_sdst[w * NNODES + idx];
        e = v > 0.f ? v : 0.01f * v;
    }
    float mx = e;
#pragma unroll
    for (int s = 16; s >= 1; s >>= 1) mx = fmaxf(mx, __shfl_xor_sync(0xffffffffu, mx, s));
    const float ex = (lane < KN) ? expf(e - mx) : 0.f;
    float sum = ex;
#pragma unroll
    for (int s = 16; s >= 1; s >>= 1) sum += __shfl_xor_sync(0xffffffffu, sum, s);
    const float alpha = ex / sum;

    __half2 ah2 = __float2half2_rn(alpha);
    const uint32_t habits = *reinterpret_cast<uint32_t*>(&ah2);

    const unsigned char* hb = g_h8 + (size_t)w * NNODES * D;   // 128 B per row
    const int sub  = lane >> 4;               // 0/1: which neighbor of the pair
    const int colb = (lane & 15) * 8;         // byte offset (8 elems) within 128B row

    __half2 acc0, acc1, acc2, acc3;
    acc0 = acc1 = acc2 = acc3 = __float2half2_rn(0.f);

#pragma unroll
    for (int i = 0; i < 8; i++) {
        const int src = 2 * i + sub;
        const uint32_t ab = __shfl_sync(0xffffffffu, habits, src);
        const int ix = __shfl_sync(0xffffffffu, idx, src);
        const uint2 v = *(const uint2*)(hb + (((unsigned)ix) << 7) + colb);
        const __half2 av = *reinterpret_cast<const __half2*>(&ab);
        acc0 = __hfma2(av, fp8x2_to_h2((unsigned short)(v.x & 0xffffu)), acc0);
        acc1 = __hfma2(av, fp8x2_to_h2((unsigned short)(v.x >> 16)),     acc1);
        acc2 = __hfma2(av, fp8x2_to_h2((unsigned short)(v.y & 0xffffu)), acc2);
        acc3 = __hfma2(av, fp8x2_to_h2((unsigned short)(v.y >> 16)),     acc3);
    }
    // combine the two half-warps (even + odd neighbors)
    {
        uint32_t b0 = *reinterpret_cast<uint32_t*>(&acc0);
        uint32_t b1 = *reinterpret_cast<uint32_t*>(&acc1);
        uint32_t b2 = *reinterpret_cast<uint32_t*>(&acc2);
        uint32_t b3 = *reinterpret_cast<uint32_t*>(&acc3);
        const uint32_t o0 = __shfl_xor_sync(0xffffffffu, b0, 16);
        const uint32_t o1 = __shfl_xor_sync(0xffffffffu, b1, 16);
        const uint32_t o2 = __shfl_xor_sync(0xffffffffu, b2, 16);
        const uint32_t o3 = __shfl_xor_sync(0xffffffffu, b3, 16);
        acc0 = __hadd2(acc0, *(const __half2*)&o0);
        acc1 = __hadd2(acc1, *(const __half2*)&o1);
        acc2 = __hadd2(acc2, *(const __half2*)&o2);
        acc3 = __hadd2(acc3, *(const __half2*)&o3);
    }
    if (lane < 16) {
        const float2 f0 = __half22float2(acc0);
        const float2 f1 = __half22float2(acc1);
        const float2 f2 = __half22float2(acc2);
        const float2 f3 = __half22float2(acc3);
        const int db = (lane & 15) * 8;
        float4* p = (float4*)&hacc[w][db];
        p[0] = make_float4(f0.x, f0.y, f1.x, f1.y);
        p[1] = make_float4(f2.x, f2.y, f3.x, f3.y);
    }
    __syncthreads();

    if (tid < D) {
        float s = 0.f;
#pragma unroll
        for (int hh = 0; hh < H; hh++) s += hacc[hh][tid];
        s *= 0.125f;                       // mean over heads
        s = s > 0.f ? s : expm1f(s);       // ELU (alpha=1)
        if (last) {
            atomicAdd(&g_gsum[tid], s);    // fused node-mean (fp32)
        } else {
            g_a8[(size_t)n * D + tid] =
                (unsigned char)__nv_cvt_float_to_fp8(s, __NV_SATFINITE, __NV_E4M3);
        }
    }
}

// ============================================================================
// Tiny MLP on g = gsum / N
// ============================================================================
__global__ void mlp_kernel(
    const float* __restrict__ ln1_g, const float* __restrict__ ln1_b,
    const float* __restrict__ lin1_W,
    const float* __restrict__ ln2_g, const float* __restrict__ ln2_b,
    const float* __restrict__ lin2_W, const float* __restrict__ lin2_b,
    const float* __restrict__ ln3_g, const float* __restrict__ ln3_b,
    const float* __restrict__ lin3_W, const float* __restrict__ lin3_b,
    const float* __restrict__ lin4_W, const float* __restrict__ lin4_b,
    float* __restrict__ out)
{
    __shared__ float buf[128];
    __shared__ float stat[2];
    const int t = threadIdx.x;   // 128 threads

    buf[t] = g_gsum[t] * (1.0f / NNODES);
    __syncthreads();

    // LN1 (len 128)
    if (t == 0) { float s=0; for (int i=0;i<128;i++) s+=buf[i]; stat[0]=s/128.f; }
    __syncthreads();
    if (t == 0) { float s=0; for (int i=0;i<128;i++){float d=buf[i]-stat[0]; s+=d*d;} stat[1]=s/128.f; }
    __syncthreads();
    float xv = (buf[t]-stat[0]) * rsqrtf(stat[1]+1e-5f) * ln1_g[t] + ln1_b[t];
    __syncthreads(); buf[t] = xv; __syncthreads();

    // lin1 (64x128, no bias) + exact GELU
    float o = 0.f;
    if (t < 64) {
        for (int d = 0; d < 128; d++) o += buf[d] * lin1_W[t*128 + d];
        o = o * normcdff(o);
    }
    __syncthreads(); if (t < 64) buf[t] = o; __syncthreads();

    // LN2 (len 64)
    if (t == 0) { float s=0; for (int i=0;i<64;i++) s+=buf[i]; stat[0]=s/64.f; }
    __syncthreads();
    if (t == 0) { float s=0; for (int i=0;i<64;i++){float d=buf[i]-stat[0]; s+=d*d;} stat[1]=s/64.f; }
    __syncthreads();
    if (t < 64) xv = (buf[t]-stat[0]) * rsqrtf(stat[1]+1e-5f) * ln2_g[t] + ln2_b[t];
    __syncthreads(); if (t < 64) buf[t] = xv; __syncthreads();

    // lin2 (32x64) + bias + GELU
    if (t < 32) {
        o = lin2_b[t];
        for (int d = 0; d < 64; d++) o += buf[d] * lin2_W[t*64 + d];
        o = o * normcdff(o);
    }
    __syncthreads(); if (t < 32) buf[t] = o; __syncthreads();

    // LN3 (len 32)
    if (t == 0) { float s=0; for (int i=0;i<32;i++) s+=buf[i]; stat[0]=s/32.f; }
    __syncthreads();
    if (t == 0) { float s=0; for (int i=0;i<32;i++){float d=buf[i]-stat[0]; s+=d*d;} stat[1]=s/32.f; }
    __syncthreads();
    if (t < 32) xv = (buf[t]-stat[0]) * rsqrtf(stat[1]+1e-5f) * ln3_g[t] + ln3_b[t];
    __syncthreads(); if (t < 32) buf[t] = xv; __syncthreads();

    // lin3 (8x32) + bias + GELU
    if (t < 8) {
        o = lin3_b[t];
        for (int d = 0; d < 32; d++) o += buf[d] * lin3_W[t*32 + d];
        o = o * normcdff(o);
    }
    __syncthreads(); if (t < 8) buf[t] = o; __syncthreads();

    // lin4 (1x8) + bias + ReLU
    if (t == 0) {
        float r = lin4_b[0];
        for (int i = 0; i < 8; i++) r += buf[i] * lin4_W[i];
        out[0] = fmaxf(r, 0.f);
    }
}

// ============================================================================
extern "C" void kernel_launch(void* const* d_in, const int* in_sizes, int n_in,
                              void* d_out, int out_size)
{
    const float* xf    = (const float*)d_in[0];
    const int*   nbr   = (const int*)  d_in[1];
    const float* W1    = (const float*)d_in[2];
    const float* a1    = (const float*)d_in[3];
    const float* W2    = (const float*)d_in[4];
    const float* a2    = (const float*)d_in[5];
    const float* W3    = (const float*)d_in[6];
    const float* a3    = (const float*)d_in[7];
    const float* ln1_g = (const float*)d_in[8];
    const float* ln1_b = (const float*)d_in[9];
    const float* lin1_W= (const float*)d_in[10];
    const float* ln2_g = (const float*)d_in[11];
    const float* ln2_b = (const float*)d_in[12];
    const float* lin2_W= (const float*)d_in[13];
    const float* lin2_b= (const float*)d_in[14];
    const float* ln3_g = (const float*)d_in[15];
    const float* ln3_b = (const float*)d_in[16];
    const float* lin3_W= (const float*)d_in[17];
    const float* lin3_b= (const float*)d_in[18];
    const float* lin4_W= (const float*)d_in[19];
    const float* lin4_b= (const float*)d_in[20];
    float* out = (float*)d_out;

    unsigned char *abp = nullptr, *wbp = nullptr;
    cudaGetSymbolAddress((void**)&abp, g_a8);
    cudaGetSymbolAddress((void**)&wbp, g_w8);

    const int WSZ = H * D * FIN;                       // 131072
    cvt_all<<<(TOTC + D + 255) / 256, 256>>>(xf, W1, W2, W3);

    const dim3 ggrid((NNODES + BM - 1) / BM, H);   // (79, 8)

    gat_gemm<<<ggrid, 256>>>(abp, wbp,            a1);
    gat_attn<<<NNODES, 256>>>(nbr, 0);
    gat_gemm<<<ggrid, 256>>>(abp, wbp + WSZ,      a2);
    gat_attn<<<NNODES, 256>>>(nbr, 0);
    gat_gemm<<<ggrid, 256>>>(abp, wbp + 2 * WSZ,  a3);
    gat_attn<<<NNODES, 256>>>(nbr, 1);

    mlp_kernel<<<1, 128>>>(ln1_g, ln1_b, lin1_W, ln2_g, ln2_b, lin2_W, lin2_b,
                           ln3_g, ln3_b, lin3_W, lin3_b, lin4_W, lin4_b, out);
    (void)in_sizes; (void)n_in; (void)out_size;
}

// round 16
// speedup vs baseline: 1.1139x; 1.0894x over previous
#include <cuda_runtime.h>
#include <cuda_bf16.h>
#include <cuda_fp8.h>
#include <stdint.h>
#include <math.h>

#define H 8
#define D 128
#define KN 16
#define NNODES 10000
#define FIN 128

// ---- scratch (static device globals; no allocation allowed) ----
__device__ unsigned char g_h8[H * NNODES * D];     // 10.2 MB fp8 (e4m3) features
__device__ unsigned char g_a8[NNODES * FIN];       // fp8 X / emb buffer (1.28 MB)
__device__ unsigned char g_w8[3 * H * D * FIN];    // fp8 weights (384 KB)
__device__ float g_ssrc[H * NNODES];
__device__ float g_sdst[H * NNODES];
__device__ float g_gsum[D];

// ============================================================================
// Merged fp32 -> fp8(e4m3) converter: X + W1 + W2 + W3, plus g_gsum zeroing.
// ============================================================================
#define NX4 (NNODES * FIN / 4)     // 320000 float4s
#define NW4 (H * D * FIN / 4)      // 32768 float4s per weight
#define TOTC (NX4 + 3 * NW4)       // 418304
__global__ void cvt_all(const float* __restrict__ x,  const float* __restrict__ w1,
                        const float* __restrict__ w2, const float* __restrict__ w3)
{
    const int i = blockIdx.x * blockDim.x + threadIdx.x;
    const float* src; unsigned char* dst; int j;
    if (i < NX4)               { src = x;  dst = g_a8;                 j = i; }
    else if (i < NX4 + NW4)    { src = w1; dst = g_w8;                 j = i - NX4; }
    else if (i < NX4 + 2*NW4)  { src = w2; dst = g_w8 + H*D*FIN;       j = i - NX4 - NW4; }
    else if (i < TOTC)         { src = w3; dst = g_w8 + 2*H*D*FIN;     j = i - NX4 - 2*NW4; }
    else {
        const int z = i - TOTC;
        if (z < D) g_gsum[z] = 0.f;
        return;
    }
    const float4 v = ((const float4*)src)[j];
    const uint32_t lo = __nv_cvt_float2_to_fp8x2(make_float2(v.x, v.y), __NV_SATFINITE, __NV_E4M3);
    const uint32_t hi = __nv_cvt_float2_to_fp8x2(make_float2(v.z, v.w), __NV_SATFINITE, __NV_E4M3);
    *(uint32_t*)(dst + j * 4) = (hi << 16) | (lo & 0xffffu);
}

// ============================================================================
// Kernel 1: per-head GEMM via FP8 tensor cores (mma.m16n8k32 e4m3, fp32 accum).
// (Frozen from round 12: best measured config.)
// ============================================================================
#define BM 128
#define AS72 72
#define TILE_B16 (BM * AS72)
#define STR 68

__device__ __forceinline__ void mma_fp8(float* c, const uint32_t* a, const uint32_t* b)
{
    asm volatile(
        "mma.sync.aligned.m16n8k32.row.col.f32.e4m3.e4m3.f32 "
        "{%0,%1,%2,%3}, {%4,%5,%6,%7}, {%8,%9}, {%0,%1,%2,%3};"
        : "+f"(c[0]), "+f"(c[1]), "+f"(c[2]), "+f"(c[3])
        : "r"(a[0]), "r"(a[1]), "r"(a[2]), "r"(a[3]), "r"(b[0]), "r"(b[1]));
}

__device__ __forceinline__ void ldsm4(uint32_t* r, uint32_t saddr)
{
    asm volatile("ldmatrix.sync.aligned.m8n8.x4.shared.b16 {%0,%1,%2,%3}, [%4];"
                 : "=r"(r[0]), "=r"(r[1]), "=r"(r[2]), "=r"(r[3]) : "r"(saddr));
}

__device__ __forceinline__ void cp16(uint32_t saddr, const void* gaddr, int srcsz)
{
    asm volatile("cp.async.cg.shared.global [%0], [%1], 16, %2;"
                 :: "r"(saddr), "l"(gaddr), "r"(srcsz));
}

__device__ __forceinline__ void cp_commit()
{ asm volatile("cp.async.commit_group;" ::: "memory"); }

__device__ __forceinline__ void cp_wait0()
{ asm volatile("cp.async.wait_group 0;" ::: "memory"); }

__global__ __launch_bounds__(256, 2) void gat_gemm(
    const unsigned char* __restrict__ A, const unsigned char* __restrict__ W,
    const float* __restrict__ avec)
{
    const int h  = blockIdx.y;
    const int n0 = blockIdx.x * BM;
    const int tid = threadIdx.x;
    const int wid = tid >> 5, lane = tid & 31;
    const int warp_m = wid >> 1;
    const int warp_n = wid & 1;
    const int g = lane >> 2, t = lane & 3;

    __shared__ __align__(16) unsigned char s_tiles[2 * TILE_B16 * 2];
    __shared__ float s_as[D], s_ad[D];

    __nv_bfloat16* As = (__nv_bfloat16*)s_tiles;
    __nv_bfloat16* Bs = (__nv_bfloat16*)(s_tiles + TILE_B16 * 2);
    float* stg = (float*)s_tiles;

    if (tid < D) {
        s_as[tid] = avec[h * 2 * D + tid];
        s_ad[tid] = avec[h * 2 * D + D + tid];
    }

    const unsigned char* Wh = W + (size_t)h * D * FIN;
    const uint32_t as_base = (uint32_t)__cvta_generic_to_shared(As);
    const uint32_t bs_base = (uint32_t)__cvta_generic_to_shared(Bs);

#pragma unroll
    for (int i = 0; i < 4; i++) {
        const int v = tid + i * 256;
        const int row = v >> 3;
        const int cb  = (v & 7) * 16;
        const uint32_t so = (uint32_t)(row * 144 + cb);
        const int gr = n0 + row;
        cp16(as_base + so, A + (size_t)gr * FIN + cb, gr < NNODES ? 16 : 0);
        cp16(bs_base + so, Wh + (size_t)row * FIN + cb, 16);
    }
    cp_commit();
    cp_wait0();
    __syncthreads();

    float acc[2][8][4];
#pragma unroll
    for (int mt = 0; mt < 2; mt++)
#pragma unroll
        for (int nt = 0; nt < 8; nt++)
#pragma unroll
            for (int i = 0; i < 4; i++) acc[mt][nt][i] = 0.f;

#pragma unroll
    for (int ks = 0; ks < 64; ks += 16) {
        uint32_t b[8][2];
#pragma unroll
        for (int np = 0; np < 4; np++) {
            const int row = warp_n * 64 + np * 16 + (lane & 7) + ((lane >> 4) << 3);
            const int col = ks + (((lane >> 3) & 1) << 3);
            uint32_t r[4];
            ldsm4(r, bs_base + (uint32_t)(row * AS72 + col) * 2);
            b[2*np][0] = r[0]; b[2*np][1] = r[1];
            b[2*np+1][0] = r[2]; b[2*np+1][1] = r[3];
        }
#pragma unroll
        for (int mt = 0; mt < 2; mt++) {
            const int row = warp_m * 32 + mt * 16 + (lane & 7) + (((lane >> 3) & 1) << 3);
            const int col = ks + ((lane >> 4) << 3);
            uint32_t a[4];
            ldsm4(a, as_base + (uint32_t)(row * AS72 + col) * 2);
#pragma unroll
            for (int nt = 0; nt < 8; nt++) mma_fp8(acc[mt][nt], a, b[nt]);
        }
    }
    __syncthreads();

    const int row  = tid >> 1;
    const int half = tid & 1;
    const int n    = n0 + row;
    float lss = 0.f, lsd = 0.f;

#pragma unroll
    for (int p = 0; p < 2; p++) {
        if (warp_n == p) {
#pragma unroll
            for (int mt = 0; mt < 2; mt++) {
                const int r0 = warp_m * 32 + mt * 16 + g;
#pragma unroll
                for (int nt = 0; nt < 8; nt++) {
                    const int c = nt * 8 + 2 * t;
                    stg[r0 * STR + c]           = acc[mt][nt][0];
                    stg[r0 * STR + c + 1]       = acc[mt][nt][1];
                    stg[(r0 + 8) * STR + c]     = acc[mt][nt][2];
                    stg[(r0 + 8) * STR + c + 1] = acc[mt][nt][3];
                }
            }
        }
        __syncthreads();

        const int cb = half * 32;
        uint32_t packed[8];
#pragma unroll
        for (int q = 0; q < 8; q++) {
            const float4 v = *(const float4*)&stg[row * STR + cb + q * 4];
            const int sc = p * 64 + cb + q * 4;
            lss += v.x * s_as[sc] + v.y * s_as[sc+1] + v.z * s_as[sc+2] + v.w * s_as[sc+3];
            lsd += v.x * s_ad[sc] + v.y * s_ad[sc+1] + v.z * s_ad[sc+2] + v.w * s_ad[sc+3];
            const uint32_t lo = __nv_cvt_float2_to_fp8x2(make_float2(v.x, v.y), __NV_SATFINITE, __NV_E4M3);
            const uint32_t hi = __nv_cvt_float2_to_fp8x2(make_float2(v.z, v.w), __NV_SATFINITE, __NV_E4M3);
            packed[q] = (hi << 16) | (lo & 0xffffu);
        }
        if (n < NNODES) {
            uint4* dst = (uint4*)&g_h8[((size_t)h * NNODES + n) * D + p * 64 + cb];
            dst[0] = make_uint4(packed[0], packed[1], packed[2], packed[3]);
            dst[1] = make_uint4(packed[4], packed[5], packed[6], packed[7]);
        }
        __syncthreads();
    }

    lss += __shfl_xor_sync(0xffffffffu, lss, 1);
    lsd += __shfl_xor_sync(0xffffffffu, lsd, 1);
    if (half == 0 && n < NNODES) {
        g_ssrc[h * NNODES + n] = lss;
        g_sdst[h * NNODES + n] = lsd;
    }
}

// ============================================================================
// Kernel 2: attention (round-12 structure: uint2 gathers, 16 lanes/row,
// 2 nbrs/iter, 4 half2 accumulators, single xor-16 combine, fp8 emb store).
// ============================================================================
__device__ __forceinline__ __half2 fp8x2_to_h2(unsigned short s)
{
    __half2_raw r = __nv_cvt_fp8x2_to_halfraw2((__nv_fp8x2_storage_t)s, __NV_E4M3);
    return *reinterpret_cast<__half2*>(&r);
}

__global__ __launch_bounds__(256) void gat_attn(const int* __restrict__ nbr)
{
    const int n = blockIdx.x;
    const int tid = threadIdx.x;
    const int w = tid >> 5, lane = tid & 31;
    __shared__ float hacc[H][D];

    int idx = 0;
    float e = -1e30f;
    if (lane < KN) {
        idx = nbr[n * KN + lane];
        const float v = g_ssrc[w * NNODES + n] + g_sdst[w * NNODES + idx];
        e = v > 0.f ? v : 0.01f * v;
    }
    float mx = e;
#pragma unroll
    for (int s = 16; s >= 1; s >>= 1) mx = fmaxf(mx, __shfl_xor_sync(0xffffffffu, mx, s));
    const float ex = (lane < KN) ? expf(e - mx) : 0.f;
    float sum = ex;
#pragma unroll
    for (int s = 16; s >= 1; s >>= 1) sum += __shfl_xor_sync(0xffffffffu, sum, s);
    const float alpha = ex / sum;

    __half2 ah2 = __float2half2_rn(alpha);
    const uint32_t habits = *reinterpret_cast<uint32_t*>(&ah2);

    const unsigned char* hb = g_h8 + (size_t)w * NNODES * D;   // 128 B per row
    const int sub  = lane >> 4;               // 0/1: which neighbor of the pair
    const int colb = (lane & 15) * 8;         // byte offset (8 elems) within 128B row

    __half2 acc0, acc1, acc2, acc3;
    acc0 = acc1 = acc2 = acc3 = __float2half2_rn(0.f);

#pragma unroll
    for (int i = 0; i < 8; i++) {
        const int src = 2 * i + sub;
        const uint32_t ab = __shfl_sync(0xffffffffu, habits, src);
        const int ix = __shfl_sync(0xffffffffu, idx, src);
        const uint2 v = *(const uint2*)(hb + (((unsigned)ix) << 7) + colb);
        const __half2 av = *reinterpret_cast<const __half2*>(&ab);
        acc0 = __hfma2(av, fp8x2_to_h2((unsigned short)(v.x & 0xffffu)), acc0);
        acc1 = __hfma2(av, fp8x2_to_h2((unsigned short)(v.x >> 16)),     acc1);
        acc2 = __hfma2(av, fp8x2_to_h2((unsigned short)(v.y & 0xffffu)), acc2);
        acc3 = __hfma2(av, fp8x2_to_h2((unsigned short)(v.y >> 16)),     acc3);
    }
    // combine the two half-warps (even + odd neighbors)
    {
        uint32_t b0 = *reinterpret_cast<uint32_t*>(&acc0);
        uint32_t b1 = *reinterpret_cast<uint32_t*>(&acc1);
        uint32_t b2 = *reinterpret_cast<uint32_t*>(&acc2);
        uint32_t b3 = *reinterpret_cast<uint32_t*>(&acc3);
        const uint32_t o0 = __shfl_xor_sync(0xffffffffu, b0, 16);
        const uint32_t o1 = __shfl_xor_sync(0xffffffffu, b1, 16);
        const uint32_t o2 = __shfl_xor_sync(0xffffffffu, b2, 16);
        const uint32_t o3 = __shfl_xor_sync(0xffffffffu, b3, 16);
        acc0 = __hadd2(acc0, *(const __half2*)&o0);
        acc1 = __hadd2(acc1, *(const __half2*)&o1);
        acc2 = __hadd2(acc2, *(const __half2*)&o2);
        acc3 = __hadd2(acc3, *(const __half2*)&o3);
    }
    if (lane < 16) {
        const float2 f0 = __half22float2(acc0);
        const float2 f1 = __half22float2(acc1);
        const float2 f2 = __half22float2(acc2);
        const float2 f3 = __half22float2(acc3);
        const int db = (lane & 15) * 8;
        float4* p = (float4*)&hacc[w][db];
        p[0] = make_float4(f0.x, f0.y, f1.x, f1.y);
        p[1] = make_float4(f2.x, f2.y, f3.x, f3.y);
    }
    __syncthreads();

    if (tid < D) {
        float s = 0.f;
#pragma unroll
        for (int hh = 0; hh < H; hh++) s += hacc[hh][tid];
        s *= 0.125f;                       // mean over heads
        s = s > 0.f ? s : expm1f(s);       // ELU (alpha=1)
        g_a8[(size_t)n * D + tid] =
            (unsigned char)__nv_cvt_float_to_fp8(s, __NV_SATFINITE, __NV_E4M3);
    }
}

// ============================================================================
// Final reduce (g = mean over nodes, emb in fp8, batched partial sums) + MLP
// ============================================================================
__global__ void reduce_kernel()
{
    const int d = threadIdx.x;                // 128 threads
    const int ns = blockIdx.x * 128;
    const int ne = min(ns + 128, NNODES);
    float s = 0.f;
    for (int n = ns; n < ne; n++) {
        __half_raw hr = __nv_cvt_fp8_to_halfraw(g_a8[(size_t)n * D + d], __NV_E4M3);
        s += __half2float(*reinterpret_cast<__half*>(&hr));
    }
    atomicAdd(&g_gsum[d], s);
}

__global__ void mlp_kernel(
    const float* __restrict__ ln1_g, const float* __restrict__ ln1_b,
    const float* __restrict__ lin1_W,
    const float* __restrict__ ln2_g, const float* __restrict__ ln2_b,
    const float* __restrict__ lin2_W, const float* __restrict__ lin2_b,
    const float* __restrict__ ln3_g, const float* __restrict__ ln3_b,
    const float* __restrict__ lin3_W, const float* __restrict__ lin3_b,
    const float* __restrict__ lin4_W, const float* __restrict__ lin4_b,
    float* __restrict__ out)
{
    __shared__ float buf[128];
    __shared__ float stat[2];
    const int t = threadIdx.x;   // 128 threads

    buf[t] = g_gsum[t] * (1.0f / NNODES);
    __syncthreads();

    // LN1 (len 128)
    if (t == 0) { float s=0; for (int i=0;i<128;i++) s+=buf[i]; stat[0]=s/128.f; }
    __syncthreads();
    if (t == 0) { float s=0; for (int i=0;i<128;i++){float d=buf[i]-stat[0]; s+=d*d;} stat[1]=s/128.f; }
    __syncthreads();
    float xv = (buf[t]-stat[0]) * rsqrtf(stat[1]+1e-5f) * ln1_g[t] + ln1_b[t];
    __syncthreads(); buf[t] = xv; __syncthreads();

    // lin1 (64x128, no bias) + exact GELU
    float o = 0.f;
    if (t < 64) {
        for (int d = 0; d < 128; d++) o += buf[d] * lin1_W[t*128 + d];
        o = o * normcdff(o);
    }
    __syncthreads(); if (t < 64) buf[t] = o; __syncthreads();

    // LN2 (len 64)
    if (t == 0) { float s=0; for (int i=0;i<64;i++) s+=buf[i]; stat[0]=s/64.f; }
    __syncthreads();
    if (t == 0) { float s=0; for (int i=0;i<64;i++){float d=buf[i]-stat[0]; s+=d*d;} stat[1]=s/64.f; }
    __syncthreads();
    if (t < 64) xv = (buf[t]-stat[0]) * rsqrtf(stat[1]+1e-5f) * ln2_g[t] + ln2_b[t];
    __syncthreads(); if (t < 64) buf[t] = xv; __syncthreads();

    // lin2 (32x64) + bias + GELU
    if (t < 32) {
        o = lin2_b[t];
        for (int d = 0; d < 64; d++) o += buf[d] * lin2_W[t*64 + d];
        o = o * normcdff(o);
    }
    __syncthreads(); if (t < 32) buf[t] = o; __syncthreads();

    // LN3 (len 32)
    if (t == 0) { float s=0; for (int i=0;i<32;i++) s+=buf[i]; stat[0]=s/32.f; }
    __syncthreads();
    if (t == 0) { float s=0; for (int i=0;i<32;i++){float d=buf[i]-stat[0]; s+=d*d;} stat[1]=s/32.f; }
    __syncthreads();
    if (t < 32) xv = (buf[t]-stat[0]) * rsqrtf(stat[1]+1e-5f) * ln3_g[t] + ln3_b[t];
    __syncthreads(); if (t < 32) buf[t] = xv; __syncthreads();

    // lin3 (8x32) + bias + GELU
    if (t < 8) {
        o = lin3_b[t];
        for (int d = 0; d < 32; d++) o += buf[d] * lin3_W[t*32 + d];
        o = o * normcdff(o);
    }
    __syncthreads(); if (t < 8) buf[t] = o; __syncthreads();

    // lin4 (1x8) + bias + ReLU
    if (t == 0) {
        float r = lin4_b[0];
        for (int i = 0; i < 8; i++) r += buf[i] * lin4_W[i];
        out[0] = fmaxf(r, 0.f);
    }
}

// ============================================================================
extern "C" void kernel_launch(void* const* d_in, const int* in_sizes, int n_in,
                              void* d_out, int out_size)
{
    const float* xf    = (const float*)d_in[0];
    const int*   nbr   = (const int*)  d_in[1];
    const float* W1    = (const float*)d_in[2];
    const float* a1    = (const float*)d_in[3];
    const float* W2    = (const float*)d_in[4];
    const float* a2    = (const float*)d_in[5];
    const float* W3    = (const float*)d_in[6];
    const float* a3    = (const float*)d_in[7];
    const float* ln1_g = (const float*)d_in[8];
    const float* ln1_b = (const float*)d_in[9];
    const float* lin1_W= (const float*)d_in[10];
    const float* ln2_g = (const float*)d_in[11];
    const float* ln2_b = (const float*)d_in[12];
    const float* lin2_W= (const float*)d_in[13];
    const float* lin2_b= (const float*)d_in[14];
    const float* ln3_g = (const float*)d_in[15];
    const float* ln3_b = (const float*)d_in[16];
    const float* lin3_W= (const float*)d_in[17];
    const float* lin3_b= (const float*)d_in[18];
    const float* lin4_W= (const float*)d_in[19];
    const float* lin4_b= (const float*)d_in[20];
    float* out = (float*)d_out;

    unsigned char *abp = nullptr, *wbp = nullptr;
    cudaGetSymbolAddress((void**)&abp, g_a8);
    cudaGetSymbolAddress((void**)&wbp, g_w8);

    const int WSZ = H * D * FIN;                       // 131072
    cvt_all<<<(TOTC + D + 255) / 256, 256>>>(xf, W1, W2, W3);

    const dim3 ggrid((NNODES + BM - 1) / BM, H);   // (79, 8)

    gat_gemm<<<ggrid, 256>>>(abp, wbp,            a1);
    gat_attn<<<NNODES, 256>>>(nbr);
    gat_gemm<<<ggrid, 256>>>(abp, wbp + WSZ,      a2);
    gat_attn<<<NNODES, 256>>>(nbr);
    gat_gemm<<<ggrid, 256>>>(abp, wbp + 2 * WSZ,  a3);
    gat_attn<<<NNODES, 256>>>(nbr);

    reduce_kernel<<<(NNODES + 127) / 128, 128>>>();
    mlp_kernel<<<1, 128>>>(ln1_g, ln1_b, lin1_W, ln2_g, ln2_b, lin2_W, lin2_b,
                           ln3_g, ln3_b, lin3_W, lin3_b, lin4_W, lin4_b, out);
    (void)in_sizes; (void)n_in; (void)out_size;
}

// round 17
// speedup vs baseline: 1.2177x; 1.0932x over previous
#include <cuda_runtime.h>
#include <cuda_bf16.h>
#include <cuda_fp16.h>
#include <cuda_fp8.h>
#include <stdint.h>
#include <math.h>

#define H 8
#define D 128
#define KN 16
#define NNODES 10000
#define FIN 128

// ---- scratch (static device globals; no allocation allowed) ----
__device__ unsigned char g_h8[H * NNODES * D];     // 10.2 MB fp8 (e4m3) features
__device__ unsigned char g_a8[NNODES * FIN];       // fp8 X / emb buffer (1.28 MB)
__device__ unsigned char g_w8[3 * H * D * FIN];    // fp8 weights (384 KB)
__device__ float g_ssrc[H * NNODES];
__device__ float g_sdst[H * NNODES];
__device__ float g_gsum[D];

// ============================================================================
// Merged fp32 -> fp8(e4m3) converter: X + W1 + W2 + W3, plus g_gsum zeroing.
// ============================================================================
#define NX4 (NNODES * FIN / 4)     // 320000 float4s
#define NW4 (H * D * FIN / 4)      // 32768 float4s per weight
#define TOTC (NX4 + 3 * NW4)       // 418304
__global__ void cvt_all(const float* __restrict__ x,  const float* __restrict__ w1,
                        const float* __restrict__ w2, const float* __restrict__ w3)
{
    const int i = blockIdx.x * blockDim.x + threadIdx.x;
    const float* src; unsigned char* dst; int j;
    if (i < NX4)               { src = x;  dst = g_a8;                 j = i; }
    else if (i < NX4 + NW4)    { src = w1; dst = g_w8;                 j = i - NX4; }
    else if (i < NX4 + 2*NW4)  { src = w2; dst = g_w8 + H*D*FIN;       j = i - NX4 - NW4; }
    else if (i < TOTC)         { src = w3; dst = g_w8 + 2*H*D*FIN;     j = i - NX4 - 2*NW4; }
    else {
        const int z = i - TOTC;
        if (z < D) g_gsum[z] = 0.f;
        return;
    }
    const float4 v = ((const float4*)src)[j];
    const uint32_t lo = __nv_cvt_float2_to_fp8x2(make_float2(v.x, v.y), __NV_SATFINITE, __NV_E4M3);
    const uint32_t hi = __nv_cvt_float2_to_fp8x2(make_float2(v.z, v.w), __NV_SATFINITE, __NV_E4M3);
    *(uint32_t*)(dst + j * 4) = (hi << 16) | (lo & 0xffffu);
}

// ============================================================================
// Kernel 1: per-head GEMM via FP8 tensor cores, fp16 accumulators
// (m16n8k32 f16.e4m3.e4m3.f16) -> 32 accum regs/thread -> 3 CTAs/SM -> 2 waves.
// Block: 128 nodes x 128 dims, full K=128 resident, 256 threads,
// warp grid 4(m) x 2(n). Epilogue staged through smem (half2 words).
// ============================================================================
#define BM 128
#define AS72 72
#define TILE_B16 (BM * AS72)
#define STR2 36                     // uint32 staging stride (144 B rows, 16B-aligned)

__device__ __forceinline__ void mma_fp8h(uint32_t* c, const uint32_t* a, const uint32_t* b)
{
    asm volatile(
        "mma.sync.aligned.m16n8k32.row.col.f16.e4m3.e4m3.f16 "
        "{%0,%1}, {%2,%3,%4,%5}, {%6,%7}, {%0,%1};"
        : "+r"(c[0]), "+r"(c[1])
        : "r"(a[0]), "r"(a[1]), "r"(a[2]), "r"(a[3]), "r"(b[0]), "r"(b[1]));
}

__device__ __forceinline__ void ldsm4(uint32_t* r, uint32_t saddr)
{
    asm volatile("ldmatrix.sync.aligned.m8n8.x4.shared.b16 {%0,%1,%2,%3}, [%4];"
                 : "=r"(r[0]), "=r"(r[1]), "=r"(r[2]), "=r"(r[3]) : "r"(saddr));
}

__device__ __forceinline__ void cp16(uint32_t saddr, const void* gaddr, int srcsz)
{
    asm volatile("cp.async.cg.shared.global [%0], [%1], 16, %2;"
                 :: "r"(saddr), "l"(gaddr), "r"(srcsz));
}

__device__ __forceinline__ void cp_commit()
{ asm volatile("cp.async.commit_group;" ::: "memory"); }

__device__ __forceinline__ void cp_wait0()
{ asm volatile("cp.async.wait_group 0;" ::: "memory"); }

__global__ __launch_bounds__(256, 3) void gat_gemm(
    const unsigned char* __restrict__ A, const unsigned char* __restrict__ W,
    const float* __restrict__ avec)
{
    const int h  = blockIdx.y;
    const int n0 = blockIdx.x * BM;
    const int tid = threadIdx.x;
    const int wid = tid >> 5, lane = tid & 31;
    const int warp_m = wid >> 1;
    const int warp_n = wid & 1;
    const int g = lane >> 2, t = lane & 3;

    __shared__ __align__(16) unsigned char s_tiles[2 * TILE_B16 * 2];
    __shared__ float s_as[D], s_ad[D];

    __nv_bfloat16* As = (__nv_bfloat16*)s_tiles;
    __nv_bfloat16* Bs = (__nv_bfloat16*)(s_tiles + TILE_B16 * 2);
    uint32_t* stg = (uint32_t*)s_tiles;      // reused as [128][STR2] half2 staging

    if (tid < D) {
        s_as[tid] = avec[h * 2 * D + tid];
        s_ad[tid] = avec[h * 2 * D + D + tid];
    }

    const unsigned char* Wh = W + (size_t)h * D * FIN;
    const uint32_t as_base = (uint32_t)__cvta_generic_to_shared(As);
    const uint32_t bs_base = (uint32_t)__cvta_generic_to_shared(Bs);

#pragma unroll
    for (int i = 0; i < 4; i++) {
        const int v = tid + i * 256;
        const int row = v >> 3;
        const int cb  = (v & 7) * 16;
        const uint32_t so = (uint32_t)(row * 144 + cb);
        const int gr = n0 + row;
        cp16(as_base + so, A + (size_t)gr * FIN + cb, gr < NNODES ? 16 : 0);
        cp16(bs_base + so, Wh + (size_t)row * FIN + cb, 16);
    }
    cp_commit();
    cp_wait0();
    __syncthreads();

    uint32_t acc[2][8][2];
#pragma unroll
    for (int mt = 0; mt < 2; mt++)
#pragma unroll
        for (int nt = 0; nt < 8; nt++) { acc[mt][nt][0] = 0u; acc[mt][nt][1] = 0u; }

#pragma unroll
    for (int ks = 0; ks < 64; ks += 16) {
        uint32_t b[8][2];
#pragma unroll
        for (int np = 0; np < 4; np++) {
            const int row = warp_n * 64 + np * 16 + (lane & 7) + ((lane >> 4) << 3);
            const int col = ks + (((lane >> 3) & 1) << 3);
            uint32_t r[4];
            ldsm4(r, bs_base + (uint32_t)(row * AS72 + col) * 2);
            b[2*np][0] = r[0]; b[2*np][1] = r[1];
            b[2*np+1][0] = r[2]; b[2*np+1][1] = r[3];
        }
#pragma unroll
        for (int mt = 0; mt < 2; mt++) {
            const int row = warp_m * 32 + mt * 16 + (lane & 7) + (((lane >> 3) & 1) << 3);
            const int col = ks + ((lane >> 4) << 3);
            uint32_t a[4];
            ldsm4(a, as_base + (uint32_t)(row * AS72 + col) * 2);
#pragma unroll
            for (int nt = 0; nt < 8; nt++) mma_fp8h(acc[mt][nt], a, b[nt]);
        }
    }
    __syncthreads();   // done reading tiles; safe to reuse as staging

    const int row  = tid >> 1;
    const int half = tid & 1;
    const int n    = n0 + row;
    float lss = 0.f, lsd = 0.f;

#pragma unroll
    for (int p = 0; p < 2; p++) {
        if (warp_n == p) {
#pragma unroll
            for (int mt = 0; mt < 2; mt++) {
                const int r0 = warp_m * 32 + mt * 16 + g;
#pragma unroll
                for (int nt = 0; nt < 8; nt++) {
                    const int c2 = nt * 4 + t;           // half2 col index
                    stg[r0 * STR2 + c2]       = acc[mt][nt][0];
                    stg[(r0 + 8) * STR2 + c2] = acc[mt][nt][1];
                }
            }
        }
        __syncthreads();

        const int cb = half * 32;                        // col base within pass
        uint32_t hw[16];
        {
            const uint4* sp = (const uint4*)&stg[row * STR2 + half * 16];
            uint4 r0 = sp[0], r1 = sp[1], r2 = sp[2], r3 = sp[3];
            hw[0]=r0.x; hw[1]=r0.y; hw[2]=r0.z; hw[3]=r0.w;
            hw[4]=r1.x; hw[5]=r1.y; hw[6]=r1.z; hw[7]=r1.w;
            hw[8]=r2.x; hw[9]=r2.y; hw[10]=r2.z; hw[11]=r2.w;
            hw[12]=r3.x; hw[13]=r3.y; hw[14]=r3.z; hw[15]=r3.w;
        }
        uint32_t packed[8];
#pragma unroll
        for (int q = 0; q < 8; q++) {
            const uint32_t wa = hw[2*q], wb = hw[2*q+1];
            const float2 fa = __half22float2(*(const __half2*)&wa);
            const float2 fb = __half22float2(*(const __half2*)&wb);
            const int sc = p * 64 + cb + q * 4;
            lss += fa.x * s_as[sc] + fa.y * s_as[sc+1] + fb.x * s_as[sc+2] + fb.y * s_as[sc+3];
            lsd += fa.x * s_ad[sc] + fa.y * s_ad[sc+1] + fb.x * s_ad[sc+2] + fb.y * s_ad[sc+3];
            __half2_raw ra; ra.x = (unsigned short)(wa & 0xffffu); ra.y = (unsigned short)(wa >> 16);
            __half2_raw rb; rb.x = (unsigned short)(wb & 0xffffu); rb.y = (unsigned short)(wb >> 16);
            const uint32_t lo = __nv_cvt_halfraw2_to_fp8x2(ra, __NV_SATFINITE, __NV_E4M3);
            const uint32_t hi = __nv_cvt_halfraw2_to_fp8x2(rb, __NV_SATFINITE, __NV_E4M3);
            packed[q] = (hi << 16) | (lo & 0xffffu);
        }
        if (n < NNODES) {
            uint4* dst = (uint4*)&g_h8[((size_t)h * NNODES + n) * D + p * 64 + cb];
            dst[0] = make_uint4(packed[0], packed[1], packed[2], packed[3]);
            dst[1] = make_uint4(packed[4], packed[5], packed[6], packed[7]);
        }
        __syncthreads();
    }

    lss += __shfl_xor_sync(0xffffffffu, lss, 1);
    lsd += __shfl_xor_sync(0xffffffffu, lsd, 1);
    if (half == 0 && n < NNODES) {
        g_ssrc[h * NNODES + n] = lss;
        g_sdst[h * NNODES + n] = lsd;
    }
}

// ============================================================================
// Kernel 2: attention (round-12 structure: uint2 gathers, 16 lanes/row,
// 2 nbrs/iter, 4 half2 accumulators, single xor-16 combine, fp8 emb store).
// ============================================================================
__device__ __forceinline__ __half2 fp8x2_to_h2(unsigned short s)
{
    __half2_raw r = __nv_cvt_fp8x2_to_halfraw2((__nv_fp8x2_storage_t)s, __NV_E4M3);
    return *reinterpret_cast<__half2*>(&r);
}

__global__ __launch_bounds__(256) void gat_attn(const int* __restrict__ nbr)
{
    const int n = blockIdx.x;
    const int tid = threadIdx.x;
    const int w = tid >> 5, lane = tid & 31;
    __shared__ float hacc[H][D];

    int idx = 0;
    float e = -1e30f;
    if (lane < KN) {
        idx = nbr[n * KN + lane];
        const float v = g_ssrc[w * NNODES + n] + g_sdst[w * NNODES + idx];
        e = v > 0.f ? v : 0.01f * v;
    }
    float mx = e;
#pragma unroll
    for (int s = 16; s >= 1; s >>= 1) mx = fmaxf(mx, __shfl_xor_sync(0xffffffffu, mx, s));
    const float ex = (lane < KN) ? expf(e - mx) : 0.f;
    float sum = ex;
#pragma unroll
    for (int s = 16; s >= 1; s >>= 1) sum += __shfl_xor_sync(0xffffffffu, sum, s);
    const float alpha = ex / sum;

    __half2 ah2 = __float2half2_rn(alpha);
    const uint32_t habits = *reinterpret_cast<uint32_t*>(&ah2);

    const unsigned char* hb = g_h8 + (size_t)w * NNODES * D;   // 128 B per row
    const int sub  = lane >> 4;               // 0/1: which neighbor of the pair
    const int colb = (lane & 15) * 8;         // byte offset (8 elems) within 128B row

    __half2 acc0, acc1, acc2, acc3;
    acc0 = acc1 = acc2 = acc3 = __float2half2_rn(0.f);

#pragma unroll
    for (int i = 0; i < 8; i++) {
        const int src = 2 * i + sub;
        const uint32_t ab = __shfl_sync(0xffffffffu, habits, src);
        const int ix = __shfl_sync(0xffffffffu, idx, src);
        const uint2 v = *(const uint2*)(hb + (((unsigned)ix) << 7) + colb);
        const __half2 av = *reinterpret_cast<const __half2*>(&ab);
        acc0 = __hfma2(av, fp8x2_to_h2((unsigned short)(v.x & 0xffffu)), acc0);
        acc1 = __hfma2(av, fp8x2_to_h2((unsigned short)(v.x >> 16)),     acc1);
        acc2 = __hfma2(av, fp8x2_to_h2((unsigned short)(v.y & 0xffffu)), acc2);
        acc3 = __hfma2(av, fp8x2_to_h2((unsigned short)(v.y >> 16)),     acc3);
    }
    // combine the two half-warps (even + odd neighbors)
    {
        uint32_t b0 = *reinterpret_cast<uint32_t*>(&acc0);
        uint32_t b1 = *reinterpret_cast<uint32_t*>(&acc1);
        uint32_t b2 = *reinterpret_cast<uint32_t*>(&acc2);
        uint32_t b3 = *reinterpret_cast<uint32_t*>(&acc3);
        const uint32_t o0 = __shfl_xor_sync(0xffffffffu, b0, 16);
        const uint32_t o1 = __shfl_xor_sync(0xffffffffu, b1, 16);
        const uint32_t o2 = __shfl_xor_sync(0xffffffffu, b2, 16);
        const uint32_t o3 = __shfl_xor_sync(0xffffffffu, b3, 16);
        acc0 = __hadd2(acc0, *(const __half2*)&o0);
        acc1 = __hadd2(acc1, *(const __half2*)&o1);
        acc2 = __hadd2(acc2, *(const __half2*)&o2);
        acc3 = __hadd2(acc3, *(const __half2*)&o3);
    }
    if (lane < 16) {
        const float2 f0 = __half22float2(acc0);
        const float2 f1 = __half22float2(acc1);
        const float2 f2 = __half22float2(acc2);
        const float2 f3 = __half22float2(acc3);
        const int db = (lane & 15) * 8;
        float4* p = (float4*)&hacc[w][db];
        p[0] = make_float4(f0.x, f0.y, f1.x, f1.y);
        p[1] = make_float4(f2.x, f2.y, f3.x, f3.y);
    }
    __syncthreads();

    if (tid < D) {
        float s = 0.f;
#pragma unroll
        for (int hh = 0; hh < H; hh++) s += hacc[hh][tid];
        s *= 0.125f;                       // mean over heads
        s = s > 0.f ? s : expm1f(s);       // ELU (alpha=1)
        g_a8[(size_t)n * D + tid] =
            (unsigned char)__nv_cvt_float_to_fp8(s, __NV_SATFINITE, __NV_E4M3);
    }
}

// ============================================================================
// Final reduce (g = mean over nodes, emb in fp8, batched partial sums) + MLP
// ============================================================================
__global__ void reduce_kernel()
{
    const int d = threadIdx.x;                // 128 threads
    const int ns = blockIdx.x * 128;
    const int ne = min(ns + 128, NNODES);
    float s = 0.f;
    for (int n = ns; n < ne; n++) {
        __half_raw hr = __nv_cvt_fp8_to_halfraw(g_a8[(size_t)n * D + d], __NV_E4M3);
        s += __half2float(*reinterpret_cast<__half*>(&hr));
    }
    atomicAdd(&g_gsum[d], s);
}

__global__ void mlp_kernel(
    const float* __restrict__ ln1_g, const float* __restrict__ ln1_b,
    const float* __restrict__ lin1_W,
    const float* __restrict__ ln2_g, const float* __restrict__ ln2_b,
    const float* __restrict__ lin2_W, const float* __restrict__ lin2_b,
    const float* __restrict__ ln3_g, const float* __restrict__ ln3_b,
    const float* __restrict__ lin3_W, const float* __restrict__ lin3_b,
    const float* __restrict__ lin4_W, const float* __restrict__ lin4_b,
    float* __restrict__ out)
{
    __shared__ float buf[128];
    __shared__ float stat[2];
    const int t = threadIdx.x;   // 128 threads

    buf[t] = g_gsum[t] * (1.0f / NNODES);
    __syncthreads();

    // LN1 (len 128)
    if (t == 0) { float s=0; for (int i=0;i<128;i++) s+=buf[i]; stat[0]=s/128.f; }
    __syncthreads();
    if (t == 0) { float s=0; for (int i=0;i<128;i++){float d=buf[i]-stat[0]; s+=d*d;} stat[1]=s/128.f; }
    __syncthreads();
    float xv = (buf[t]-stat[0]) * rsqrtf(stat[1]+1e-5f) * ln1_g[t] + ln1_b[t];
    __syncthreads(); buf[t] = xv; __syncthreads();

    // lin1 (64x128, no bias) + exact GELU
    float o = 0.f;
    if (t < 64) {
        for (int d = 0; d < 128; d++) o += buf[d] * lin1_W[t*128 + d];
        o = o * normcdff(o);
    }
    __syncthreads(); if (t < 64) buf[t] = o; __syncthreads();

    // LN2 (len 64)
    if (t == 0) { float s=0; for (int i=0;i<64;i++) s+=buf[i]; stat[0]=s/64.f; }
    __syncthreads();
    if (t == 0) { float s=0; for (int i=0;i<64;i++){float d=buf[i]-stat[0]; s+=d*d;} stat[1]=s/64.f; }
    __syncthreads();
    if (t < 64) xv = (buf[t]-stat[0]) * rsqrtf(stat[1]+1e-5f) * ln2_g[t] + ln2_b[t];
    __syncthreads(); if (t < 64) buf[t] = xv; __syncthreads();

    // lin2 (32x64) + bias + GELU
    if (t < 32) {
        o = lin2_b[t];
        for (int d = 0; d < 64; d++) o += buf[d] * lin2_W[t*64 + d];
        o = o * normcdff(o);
    }
    __syncthreads(); if (t < 32) buf[t] = o; __syncthreads();

    // LN3 (len 32)
    if (t == 0) { float s=0; for (int i=0;i<32;i++) s+=buf[i]; stat[0]=s/32.f; }
    __syncthreads();
    if (t == 0) { float s=0; for (int i=0;i<32;i++){float d=buf[i]-stat[0]; s+=d*d;} stat[1]=s/32.f; }
    __syncthreads();
    if (t < 32) xv = (buf[t]-stat[0]) * rsqrtf(stat[1]+1e-5f) * ln3_g[t] + ln3_b[t];
    __syncthreads(); if (t < 32) buf[t] = xv; __syncthreads();

    // lin3 (8x32) + bias + GELU
    if (t < 8) {
        o = lin3_b[t];
        for (int d = 0; d < 32; d++) o += buf[d] * lin3_W[t*32 + d];
        o = o * normcdff(o);
    }
    __syncthreads(); if (t < 8) buf[t] = o; __syncthreads();

    // lin4 (1x8) + bias + ReLU
    if (t == 0) {
        float r = lin4_b[0];
        for (int i = 0; i < 8; i++) r += buf[i] * lin4_W[i];
        out[0] = fmaxf(r, 0.f);
    }
}

// ============================================================================
extern "C" void kernel_launch(void* const* d_in, const int* in_sizes, int n_in,
                              void* d_out, int out_size)
{
    const float* xf    = (const float*)d_in[0];
    const int*   nbr   = (const int*)  d_in[1];
    const float* W1    = (const float*)d_in[2];
    const float* a1    = (const float*)d_in[3];
    const float* W2    = (const float*)d_in[4];
    const float* a2    = (const float*)d_in[5];
    const float* W3    = (const float*)d_in[6];
    const float* a3    = (const float*)d_in[7];
    const float* ln1_g = (const float*)d_in[8];
    const float* ln1_b = (const float*)d_in[9];
    const float* lin1_W= (const float*)d_in[10];
    const float* ln2_g = (const float*)d_in[11];
    const float* ln2_b = (const float*)d_in[12];
    const float* lin2_W= (const float*)d_in[13];
    const float* lin2_b= (const float*)d_in[14];
    const float* ln3_g = (const float*)d_in[15];
    const float* ln3_b = (const float*)d_in[16];
    const float* lin3_W= (const float*)d_in[17];
    const float* lin3_b= (const float*)d_in[18];
    const float* lin4_W= (const float*)d_in[19];
    const float* lin4_b= (const float*)d_in[20];
    float* out = (float*)d_out;

    unsigned char *abp = nullptr, *wbp = nullptr;
    cudaGetSymbolAddress((void**)&abp, g_a8);
    cudaGetSymbolAddress((void**)&wbp, g_w8);

    const int WSZ = H * D * FIN;                       // 131072
    cvt_all<<<(TOTC + D + 255) / 256, 256>>>(xf, W1, W2, W3);

    const dim3 ggrid((NNODES + BM - 1) / BM, H);   // (79, 8)

    gat_gemm<<<ggrid, 256>>>(abp, wbp,            a1);
    gat_attn<<<NNODES, 256>>>(nbr);
    gat_gemm<<<ggrid, 256>>>(abp, wbp + WSZ,      a2);
    gat_attn<<<NNODES, 256>>>(nbr);
    gat_gemm<<<ggrid, 256>>>(abp, wbp + 2 * WSZ,  a3);
    gat_attn<<<NNODES, 256>>>(nbr);

    reduce_kernel<<<(NNODES + 127) / 128, 128>>>();
    mlp_kernel<<<1, 128>>>(ln1_g, ln1_b, lin1_W, ln2_g, ln2_b, lin2_W, lin2_b,
                           ln3_g, ln3_b, lin3_W, lin3_b, lin4_W, lin4_b, out);
    (void)in_sizes; (void)n_in; (void)out_size;
}